// round 15
// baseline (speedup 1.0000x reference)
#include <cuda_runtime.h>
#include <cuda_bf16.h>

// Problem constants
#define B_    64
#define C_    2048
#define HW_   576
#define HW4_  144            // HW_/4 float4 groups per channel row
#define NBLK  32             // tiles per (t,b): 64 channels each
#define CPS   16             // channels per (block, csub)
#define NGRID 4096           // NBLK * B_ * 2
#define NCLS  16             // NUM_CLASSES
#define ACCTOT (2 * B_ * HW_)   // 73728 floats per parity buffer

// Scratch (allocation-free rule: __device__ globals; zero at module load).
// g_lum[par][t][b][p]: t=0 -> lum_v, t=1 -> lum_i (row-major; no transpose
// needed by the class-factored finish). Parity ping-pong: launch N
// accumulates par, zeroes 1-par; the finalize thread flips par at the end.
// Tickets g_t1/g_t2 are NEVER reset: exactly 4096 / 64 increments per
// launch, position = count & (N-1). Wrap-free, replay-safe.
__device__ float        g_lum[2][2][B_][HW_];
__device__ int          g_parity;
__device__ double       g_sum;     // reset by its unique last reader
__device__ int          g_cnt;
__device__ unsigned int g_t1;      // block-completion ticket (4096/launch)
__device__ unsigned int g_t2;      // crew-finalize ticket    (64/launch)

// ---------------------------------------------------------------------------
// SINGLE kernel. grid = (NBLK, B, 2) = 4096 blocks, block = 576, 3/SM.
// Stream (frozen ~87us pattern): float4 loads, smem fold, 4 REDG.F32
//   atomicAdd into g_lum[par][t][b]. Zeroes other parity (18 fl/block).
// Tail: each block fences, takes a t1 ticket. The last 64 takers are the
//   crew; crew block i waits for all 4096, then runs the CLASS-FACTORED
//   finish (validated in R14):
//     total = sum_i (n_i-1)(|lv_i|^2+|li_i|^2) + 2 sum_i lv_i.li_i
//           - 2 sum_c U_c.W_c ,  loss = total / HW / npairs.
//   Per-thread: ONE product (p = tid) + (i<16) class-sum loop in fp32.
//   Double shuffle reduce, t2-ticket finalize, flip parity.
// Labels are int32 (JAX x64 disabled).
// ---------------------------------------------------------------------------
__global__ void __launch_bounds__(576, 3)
k_fused(const float* __restrict__ fv, const float* __restrict__ fi,
        const int* __restrict__ labels, float* __restrict__ out) {
    const int blk  = blockIdx.x;
    const int b    = blockIdx.y;
    const int t    = blockIdx.z;
    const int tid  = threadIdx.x;
    const int q    = tid % HW4_;
    const int csub = tid / HW4_;

    const int par = g_parity;

    // Zero the other parity buffer: 73728 floats / 4096 blocks = 18 each.
    {
        const int blin = blk + NBLK * (b + B_ * t);    // 0..4095
        if (tid < 18) ((float*)g_lum[1 - par])[blin * 18 + tid] = 0.0f;
    }

    // ---- streaming sum-of-squares ----
    const float* __restrict__ f = t ? fi : fv;
    const float4* __restrict__ base = (const float4*)
        (f + ((size_t)b * C_ + (size_t)blk * 64) * HW_)
        + (size_t)csub * CPS * HW4_ + q;

    float ax = 0.f, ay = 0.f, az = 0.f, aw = 0.f;
#pragma unroll 8
    for (int it = 0; it < CPS; ++it) {
        float4 x = base[(size_t)it * HW4_];
        ax = fmaf(x.x, x.x, ax);
        ay = fmaf(x.y, x.y, ay);
        az = fmaf(x.z, x.z, az);
        aw = fmaf(x.w, x.w, aw);
    }

    __shared__ float4 sh[4][HW4_];
    sh[csub][q] = make_float4(ax, ay, az, aw);
    __syncthreads();

    if (csub == 0) {
        float4 a = sh[0][q], c1 = sh[1][q], c2 = sh[2][q], c3 = sh[3][q];
        a.x += c1.x + c2.x + c3.x;
        a.y += c1.y + c2.y + c3.y;
        a.z += c1.z + c2.z + c3.z;
        a.w += c1.w + c2.w + c3.w;
        float* dst = &g_lum[par][t][b][4 * q];
        atomicAdd(dst + 0, a.x);
        atomicAdd(dst + 1, a.y);
        atomicAdd(dst + 2, a.z);
        atomicAdd(dst + 3, a.w);
    }

    // ---- ticket: publish this block's contribution ----
    __threadfence();
    __syncthreads();
    __shared__ unsigned s_tk;
    if (tid == 0) s_tk = atomicAdd(&g_t1, 1u);
    __syncthreads();
    const unsigned my  = s_tk;
    const unsigned pos = my & (NGRID - 1);            // 0..4095 within launch
    if (pos < NGRID - B_) return;                     // not crew -> done
    const unsigned base_t = my - pos;                 // launch epoch base

    // ---- crew: wait for all 4096 blocks of this launch ----
    if (tid == 0) {
        while (atomicAdd(&g_t1, 0u) - base_t < NGRID) __nanosleep(64);
    }
    __syncthreads();
    __threadfence();                                  // acquire

    // ---- class-factored finish: crew row i, thread p = tid ----
    const int i    = (int)(pos - (NGRID - B_));       // 0..63
    const int lane = tid & 31;
    const int wid  = tid >> 5;                        // 0..17

    __shared__ int s_lab[B_];
    if (tid < B_) s_lab[tid] = labels[tid];
    __syncthreads();

    const float lvf = g_lum[par][0][i][tid];
    const float lif = g_lum[par][1][i][tid];
    double v2 = (double)lvf * (double)lvf;
    double i2 = (double)lif * (double)lif;
    double dd = (double)lvf * (double)lif;

    // class dot for c = i (blocks 0..15): U_c[p], W_c[p] summed in fp32
    double uw = 0.0;
    if (i < NCLS) {
        float u = 0.f, w = 0.f;
        for (int jj = 0; jj < B_; ++jj) {
            if (s_lab[jj] == i) {
                u += g_lum[par][0][jj][tid];
                w += g_lum[par][1][jj][tid];
            }
        }
        uw = (double)u * (double)w;
    }

#pragma unroll
    for (int off = 16; off > 0; off >>= 1) {
        v2 += __shfl_down_sync(0xffffffffu, v2, off);
        i2 += __shfl_down_sync(0xffffffffu, i2, off);
        dd += __shfl_down_sync(0xffffffffu, dd, off);
        uw += __shfl_down_sync(0xffffffffu, uw, off);
    }

    __shared__ double s_v2[18], s_i2[18], s_dd[18], s_uw[18];
    if (lane == 0) { s_v2[wid] = v2; s_i2[wid] = i2; s_dd[wid] = dd; s_uw[wid] = uw; }

    // n_i = |{j : labels[j] == labels[i]}| (includes i)
    const bool m = (tid < B_) && (s_lab[tid] == s_lab[i]);
    const int n_i = __syncthreads_count(m);           // also orders s_* writes

    if (tid == 0) {
        double V2 = 0.0, I2 = 0.0, DD = 0.0, UW = 0.0;
#pragma unroll
        for (int k = 0; k < 18; ++k) {
            V2 += s_v2[k]; I2 += s_i2[k]; DD += s_dd[k]; UW += s_uw[k];
        }
        double contrib = (double)(n_i - 1) * (V2 + I2) + 2.0 * DD;
        if (i < NCLS) contrib -= 2.0 * UW;

        atomicAdd(&g_sum, contrib);
        atomicAdd(&g_cnt, n_i - 1);
        __threadfence();
        const unsigned tk2 = atomicAdd(&g_t2, 1u);
        if ((tk2 & (B_ - 1)) == B_ - 1) {             // last of this launch's 64
            const double total = atomicAdd(&g_sum, 0.0);   // atomic read
            const int    cnt   = atomicAdd(&g_cnt, 0);     // npairs
            out[0] = (cnt > 0)
                   ? (float)(total / (double)HW_ / (double)cnt) : 0.0f;
            g_sum = 0.0; g_cnt = 0;                   // unique last reader resets
            g_parity = par ^ 1;                       // flip for next replay
            __threadfence();
        }
    }
}

extern "C" void kernel_launch(void* const* d_in, const int* in_sizes, int n_in,
                              void* d_out, int out_size) {
    const float* fv     = (const float*)d_in[0];
    const float* fi     = (const float*)d_in[1];
    const int*   labels = (const int*)d_in[2];
    float*       out    = (float*)d_out;

    k_fused<<<dim3(NBLK, B_, 2), 576>>>(fv, fi, labels, out);
}

// round 16
// speedup vs baseline: 1.1696x; 1.1696x over previous
#include <cuda_runtime.h>
#include <cuda_bf16.h>

// Problem constants
#define B_    64
#define C_    2048
#define HW_   576
#define HW4_  144          // HW_/4 float4 groups per channel row
#define NBLK  32           // k1 tiles per (t,b): 64 channels each
#define CPS   16           // channels per (block, csub)
#define NCLS  16           // NUM_CLASSES
#define LUMN  (2 * B_ * HW_)   // 73728 floats per parity buffer

// Scratch (allocation-free rule: __device__ globals; zero at module load).
// g_lum[par][t][b][p]: t=0 -> lum_v, t=1 -> lum_i (row-major only; the
// class-factored finish needs no transpose). Parity ping-pong: k1(N)
// accumulates par, zeroes 1-par; k2(N) flips par at the very end.
__device__ float        g_lum[2][2][B_][HW_];
__device__ int          g_parity;
__device__ double       g_sum;
__device__ int          g_cnt;
__device__ unsigned int g_ticket;

// ---------------------------------------------------------------------------
// Kernel 1 (frozen ~87us stream): float4 loads, smem fold, 4 REDG.F32
// atomicAdd into g_lum[par][t][b] (lumT atomics DROPPED vs R13 -> fewer).
// Zeroes other parity buffer (18 floats/block) + scalar reduction state.
// Ends with the PDL trigger so k_finish can spin up during our ramp-down.
// grid = (NBLK, B, 2) = 4096 blocks, block = 576, 3 blocks/SM.
// ---------------------------------------------------------------------------
__global__ void __launch_bounds__(576, 3)
k_lum_partial(const float* __restrict__ fv, const float* __restrict__ fi) {
    const int blk  = blockIdx.x;
    const int b    = blockIdx.y;
    const int t    = blockIdx.z;
    const int tid  = threadIdx.x;
    const int q    = tid % HW4_;
    const int csub = tid / HW4_;

    const int par = g_parity;

    if (blk == 0 && b == 0 && t == 0 && tid == 0) {
        g_sum = 0.0; g_cnt = 0; g_ticket = 0u;
    }

    // Zero the other parity buffer: 73728 floats / 4096 blocks = 18 each.
    {
        const int blin = blk + NBLK * (b + B_ * t);    // 0..4095
        if (tid < 18) ((float*)g_lum[1 - par])[blin * 18 + tid] = 0.0f;
    }

    const float* __restrict__ f = t ? fi : fv;
    const float4* __restrict__ base = (const float4*)
        (f + ((size_t)b * C_ + (size_t)blk * 64) * HW_)
        + (size_t)csub * CPS * HW4_ + q;

    float ax = 0.f, ay = 0.f, az = 0.f, aw = 0.f;
#pragma unroll 8
    for (int it = 0; it < CPS; ++it) {
        float4 x = base[(size_t)it * HW4_];
        ax = fmaf(x.x, x.x, ax);
        ay = fmaf(x.y, x.y, ay);
        az = fmaf(x.z, x.z, az);
        aw = fmaf(x.w, x.w, aw);
    }

    __shared__ float4 sh[4][HW4_];
    sh[csub][q] = make_float4(ax, ay, az, aw);
    __syncthreads();

    if (csub == 0) {
        float4 a = sh[0][q], c1 = sh[1][q], c2 = sh[2][q], c3 = sh[3][q];
        a.x += c1.x + c2.x + c3.x;
        a.y += c1.y + c2.y + c3.y;
        a.z += c1.z + c2.z + c3.z;
        a.w += c1.w + c2.w + c3.w;
        float* dst = &g_lum[par][t][b][4 * q];
        atomicAdd(dst + 0, a.x);
        atomicAdd(dst + 1, a.y);
        atomicAdd(dst + 2, a.z);
        atomicAdd(dst + 3, a.w);
    }
    __syncthreads();                 // all CTA writes precede the trigger

    // PDL: this CTA's work is published; dependent grid may begin launching.
    cudaTriggerProgrammaticLaunchCompletion();
}

// ---------------------------------------------------------------------------
// Kernel 2: class-factored finish (validated R14/R15), PDL-overlapped.
// grid = 64, block = 576. Prologue (labels -> smem) runs BEFORE the grid
// dependency sync, overlapping k1's tail. Then:
//   total = sum_i (n_i-1)(|lv_i|^2+|li_i|^2) + 2 sum_i lv_i.li_i
//         - 2 sum_c U_c.W_c ,  loss = total / HW / npairs.
// Block i: one product per thread (p = tid); blocks 0..15 also build the
// class-sum dot (fp32 member loop -> double product). Shuffle reduce,
// ticket finalize, parity flip. Labels are int32 (JAX x64 disabled).
// ---------------------------------------------------------------------------
__global__ void __launch_bounds__(576, 2)
k_finish(const int* __restrict__ labels, float* __restrict__ out) {
    const int i    = blockIdx.x;   // 0..63
    const int tid  = threadIdx.x;  // 0..575
    const int lane = tid & 31;
    const int wid  = tid >> 5;     // 0..17

    // ---- prologue (overlaps k1 tail under PDL) ----
    __shared__ int s_lab[B_];
    if (tid < B_) s_lab[tid] = labels[tid];
    __syncthreads();
    const int par = g_parity;      // stable during k1 (flipped only by k2)

    // ---- wait for k1's memory to be visible ----
    cudaGridDependencySynchronize();

    const float lvf = g_lum[par][0][i][tid];
    const float lif = g_lum[par][1][i][tid];
    double v2 = (double)lvf * (double)lvf;
    double i2 = (double)lif * (double)lif;
    double dd = (double)lvf * (double)lif;

    // class dot for c = i (blocks 0..15): U_c[p], W_c[p] summed in fp32
    double uw = 0.0;
    if (i < NCLS) {
        float u = 0.f, w = 0.f;
        for (int jj = 0; jj < B_; ++jj) {
            if (s_lab[jj] == i) {
                u += g_lum[par][0][jj][tid];
                w += g_lum[par][1][jj][tid];
            }
        }
        uw = (double)u * (double)w;
    }

#pragma unroll
    for (int off = 16; off > 0; off >>= 1) {
        v2 += __shfl_down_sync(0xffffffffu, v2, off);
        i2 += __shfl_down_sync(0xffffffffu, i2, off);
        dd += __shfl_down_sync(0xffffffffu, dd, off);
        uw += __shfl_down_sync(0xffffffffu, uw, off);
    }

    __shared__ double s_v2[18], s_i2[18], s_dd[18], s_uw[18];
    if (lane == 0) { s_v2[wid] = v2; s_i2[wid] = i2; s_dd[wid] = dd; s_uw[wid] = uw; }

    // n_i = |{j : labels[j] == labels[i]}| (includes i)
    const bool m = (tid < B_) && (s_lab[tid] == s_lab[i]);
    const int n_i = __syncthreads_count(m);   // also orders s_* writes

    if (tid == 0) {
        double V2 = 0.0, I2 = 0.0, DD = 0.0, UW = 0.0;
#pragma unroll
        for (int k = 0; k < 18; ++k) {
            V2 += s_v2[k]; I2 += s_i2[k]; DD += s_dd[k]; UW += s_uw[k];
        }
        double contrib = (double)(n_i - 1) * (V2 + I2) + 2.0 * DD;
        if (i < NCLS) contrib -= 2.0 * UW;

        atomicAdd(&g_sum, contrib);
        atomicAdd(&g_cnt, n_i - 1);
        __threadfence();
        const unsigned tk = atomicAdd(&g_ticket, 1u);
        if (tk == B_ - 1) {
            const double total = atomicAdd(&g_sum, 0.0);  // atomic read
            const int    cnt   = atomicAdd(&g_cnt, 0);    // npairs
            out[0] = (cnt > 0)
                   ? (float)(total / (double)HW_ / (double)cnt) : 0.0f;
            g_parity = par ^ 1;                           // flip for next replay
            __threadfence();
        }
    }
}

extern "C" void kernel_launch(void* const* d_in, const int* in_sizes, int n_in,
                              void* d_out, int out_size) {
    const float* fv     = (const float*)d_in[0];
    const float* fi     = (const float*)d_in[1];
    const int*   labels = (const int*)d_in[2];
    float*       out    = (float*)d_out;

    k_lum_partial<<<dim3(NBLK, B_, 2), 576>>>(fv, fi);

    // PDL launch: k_finish spins up during k1's ramp-down.
    cudaLaunchConfig_t cfg = {};
    cfg.gridDim       = dim3(B_, 1, 1);
    cfg.blockDim      = dim3(576, 1, 1);
    cfg.dynamicSmemBytes = 0;
    cfg.stream        = 0;
    cudaLaunchAttribute attr[1];
    attr[0].id = cudaLaunchAttributeProgrammaticStreamSerialization;
    attr[0].val.programmaticStreamSerializationAllowed = 1;
    cfg.attrs    = attr;
    cfg.numAttrs = 1;
    cudaLaunchKernelEx(&cfg, k_finish, labels, (float*)d_out);
}